// round 1
// baseline (speedup 1.0000x reference)
#include <cuda_runtime.h>
#include <math.h>

#define MULC 64
#define NRAD 8
#define MAX_EDGES 320000

// 320000 * 256 floats = 327.68 MB scratch for per-edge MLP output ("mix")
__device__ float g_mix[(size_t)MAX_EDGES * 256];

__device__ __forceinline__ float silu_act(float x, float act_cst) {
    float s = __fdividef(x, 1.0f + __expf(-x));
    return s * act_cst;
}

// ---------------------------------------------------------------------------
// Kernel 1: per-edge MLP. One thread = one edge. Weights transposed in smem
// (all reads warp-uniform broadcasts -> conflict free). h1/h2 register-resident.
// ---------------------------------------------------------------------------
extern __shared__ float k1_smem[];

__global__ void __launch_bounds__(256, 1)
mlp_kernel(const float* __restrict__ edge_attrs,
           const float* __restrict__ w0, const float* __restrict__ w1,
           const float* __restrict__ w2, const float* __restrict__ w3,
           int n_edges, float act_cst)
{
    float* sw0 = k1_smem;            // [64][8]   transposed: sw0[j*8+k]   = w0[k*64+j]
    float* sw1 = sw0 + 64 * 8;       // [64][64]  sw1[j*64+k]  = w1[k*64+j]
    float* sw2 = sw1 + 64 * 64;      // [64][64]
    float* sw3 = sw2 + 64 * 64;      // [256][64] sw3[o*64+k]  = w3[k*256+o]

    for (int i = threadIdx.x; i < 64 * 8; i += blockDim.x) {
        int j = i >> 3, k = i & 7;
        sw0[i] = w0[k * 64 + j];
    }
    for (int i = threadIdx.x; i < 64 * 64; i += blockDim.x) {
        int j = i >> 6, k = i & 63;
        sw1[i] = w1[k * 64 + j];
        sw2[i] = w2[k * 64 + j];
    }
    for (int i = threadIdx.x; i < 256 * 64; i += blockDim.x) {
        int o = i >> 6, k = i & 63;
        sw3[i] = w3[k * 256 + o];
    }
    __syncthreads();

    int e = blockIdx.x * blockDim.x + threadIdx.x;
    if (e >= n_edges) return;

    const float* ea = edge_attrs + (size_t)e * 11;
    float x[8];
#pragma unroll
    for (int k = 0; k < 8; k++) x[k] = __ldg(ea + k);

    const float inv_sqrt8 = 0.35355339059327373f;

    float h1[64];
#pragma unroll
    for (int j = 0; j < 64; j++) {
        float acc = 0.0f;
#pragma unroll
        for (int k = 0; k < 8; k++) acc = fmaf(x[k], sw0[j * 8 + k], acc);
        h1[j] = silu_act(acc * inv_sqrt8, act_cst);
    }

    float h2[64];
#pragma unroll
    for (int j = 0; j < 64; j++) {
        float acc = 0.0f;
#pragma unroll
        for (int k = 0; k < 64; k++) acc = fmaf(h1[k], sw1[j * 64 + k], acc);
        h2[j] = silu_act(acc * 0.125f, act_cst);
    }

#pragma unroll
    for (int j = 0; j < 64; j++) {
        float acc = 0.0f;
#pragma unroll
        for (int k = 0; k < 64; k++) acc = fmaf(h2[k], sw2[j * 64 + k], acc);
        h1[j] = silu_act(acc * 0.125f, act_cst);   // h3 reuses h1's registers
    }

    // Final layer: 256 outputs, 4 at a time, stored as float4 (no activation).
    float4* outp = (float4*)(g_mix + (size_t)e * 256);
    for (int o = 0; o < 256; o += 4) {
        float a0 = 0.f, a1 = 0.f, a2 = 0.f, a3 = 0.f;
        const float* r0 = sw3 + (o + 0) * 64;
        const float* r1 = sw3 + (o + 1) * 64;
        const float* r2 = sw3 + (o + 2) * 64;
        const float* r3 = sw3 + (o + 3) * 64;
#pragma unroll
        for (int k = 0; k < 64; k++) {
            float h = h1[k];
            a0 = fmaf(h, r0[k], a0);
            a1 = fmaf(h, r1[k], a1);
            a2 = fmaf(h, r2[k], a2);
            a3 = fmaf(h, r3[k], a3);
        }
        outp[o >> 2] = make_float4(a0 * 0.125f, a1 * 0.125f, a2 * 0.125f, a3 * 0.125f);
    }
}

// ---------------------------------------------------------------------------
// Kernel 2: warp-per-edge message build + vectorized scatter-add.
// Stage the 512-float message in smem, flush with red.global.add.v4.f32.
// ---------------------------------------------------------------------------
__global__ void __launch_bounds__(256)
scatter_kernel(const float* __restrict__ node_feats,
               const float* __restrict__ edge_attrs,
               const int* __restrict__ senders,
               const int* __restrict__ receivers,
               float* __restrict__ out,
               int n_edges)
{
    __shared__ float msg[8][512];
    int warp = threadIdx.x >> 5;
    int lane = threadIdx.x & 31;
    int e = blockIdx.x * 8 + warp;
    if (e >= n_edges) return;           // warp-uniform exit

    int s = __ldg(senders + e);
    int r = __ldg(receivers + e);
    const float* ea = edge_attrs + (size_t)e * 11;
    float ev0 = __ldg(ea + 8), ev1 = __ldg(ea + 9), ev2 = __ldg(ea + 10);

    const float* nrow   = node_feats + (size_t)s * 256;
    const float* mixrow = g_mix + (size_t)e * 256;

    const float S   = 0.25f;                    // 1/sqrt(16)
    const float IS3 = 0.57735026918962576f;     // 1/sqrt(3)

#pragma unroll
    for (int t = 0; t < 2; t++) {
        int m = lane + t * 32;
        float ms = __ldg(nrow + m);
        float v0 = __ldg(nrow + 64 + 3 * m + 0);
        float v1 = __ldg(nrow + 64 + 3 * m + 1);
        float v2 = __ldg(nrow + 64 + 3 * m + 2);
        float mixA = __ldg(mixrow + m);
        float mixB = __ldg(mixrow + 64 + m);
        float mixC = __ldg(mixrow + 128 + m);
        float mixD = __ldg(mixrow + 192 + m);

        float tps = (v0 * ev0 + v1 * ev1 + v2 * ev2) * IS3;

        msg[warp][m]      = ms  * mixA * S;      // out_s, channel m
        msg[warp][64 + m] = tps * mixB * S;      // out_s, channel 64+m

        float c = mixC * S;                      // out_v channels 0..63: mv * mix
        msg[warp][128 + 3 * m + 0] = v0 * c;
        msg[warp][128 + 3 * m + 1] = v1 * c;
        msg[warp][128 + 3 * m + 2] = v2 * c;

        float d = ms * mixD * S;                 // out_v channels 64..127: ms*ev * mix
        msg[warp][320 + 3 * m + 0] = ev0 * d;
        msg[warp][320 + 3 * m + 1] = ev1 * d;
        msg[warp][320 + 3 * m + 2] = ev2 * d;
    }
    __syncwarp();

    float* orow = out + (size_t)r * 512;
    const float4* m4 = (const float4*)msg[warp];
#pragma unroll
    for (int i = 0; i < 4; i++) {
        int idx = lane + i * 32;
        float4 v = m4[idx];
        asm volatile("red.global.add.v4.f32 [%0], {%1, %2, %3, %4};"
                     :: "l"(orow + idx * 4),
                        "f"(v.x), "f"(v.y), "f"(v.z), "f"(v.w)
                     : "memory");
    }
}

// ---------------------------------------------------------------------------
// Host: ACT_CST = 1/sqrt(E[silu(X)^2]), X~N(0,1). Simpson in double matches
// the reference's hermegauss(128) quadrature to far below 1e-6.
// ---------------------------------------------------------------------------
static float compute_act_cst() {
    const int    N = 20000;
    const double a = -14.0, b = 14.0;
    const double h = (b - a) / N;
    double sum = 0.0;
    for (int i = 0; i <= N; i++) {
        double xx  = a + h * i;
        double sig = 1.0 / (1.0 + exp(-xx));
        double sl  = xx * sig;
        double f   = exp(-0.5 * xx * xx) * sl * sl;
        double wq  = (i == 0 || i == N) ? 1.0 : ((i & 1) ? 4.0 : 2.0);
        sum += wq * f;
    }
    sum *= h / 3.0;
    sum /= sqrt(2.0 * M_PI);
    return (float)(1.0 / sqrt(sum));
}

extern "C" void kernel_launch(void* const* d_in, const int* in_sizes, int n_in,
                              void* d_out, int out_size)
{
    const float* node_feats = (const float*)d_in[0];
    const float* edge_attrs = (const float*)d_in[1];
    const int*   senders    = (const int*)d_in[2];
    const int*   receivers  = (const int*)d_in[3];
    const float* w0         = (const float*)d_in[4];
    const float* w1         = (const float*)d_in[5];
    const float* w2         = (const float*)d_in[6];
    const float* w3         = (const float*)d_in[7];
    float*       out        = (float*)d_out;

    int n_edges = in_sizes[2];
    if (n_edges > MAX_EDGES) n_edges = MAX_EDGES;

    float act_cst = compute_act_cst();

    // Zero the (0xAA-poisoned) output accumulator.
    cudaMemsetAsync(d_out, 0, (size_t)out_size * sizeof(float));

    // Kernel 1: per-edge MLP -> g_mix
    const int k1_smem_bytes = (64 * 8 + 64 * 64 + 64 * 64 + 256 * 64) * (int)sizeof(float);
    cudaFuncSetAttribute(mlp_kernel, cudaFuncAttributeMaxDynamicSharedMemorySize,
                         k1_smem_bytes);
    int k1_blocks = (n_edges + 255) / 256;
    mlp_kernel<<<k1_blocks, 256, k1_smem_bytes>>>(edge_attrs, w0, w1, w2, w3,
                                                  n_edges, act_cst);

    // Kernel 2: message build + vectorized scatter-add
    int k2_blocks = (n_edges + 7) / 8;
    scatter_kernel<<<k2_blocks, 256>>>(node_feats, edge_attrs, senders, receivers,
                                       out, n_edges);
}

// round 3
// speedup vs baseline: 3.1262x; 3.1262x over previous
#include <cuda_runtime.h>
#include <cuda_bf16.h>
#include <math.h>
#include <stdint.h>

#define MAX_EDGES 320000

// 320000 * 256 floats scratch for per-edge MLP output ("mix")
__device__ float g_mix[(size_t)MAX_EDGES * 256];

// Weight fragments, B-operand layout for mma.m16n8k16 (col-major B), hi/lo split.
// Entry = uint4 {b0_hi, b1_hi, b0_lo, b1_lo} per lane.
// L1: ntiles=8, ktiles=1 ->  256 entries  [0, 256)
// L2: 8x4                -> 1024 entries  [256, 1280)
// L3: 8x4                -> 1024 entries  [1280, 2304)
// L4: 32x4               -> 4096 entries  [2304, 6400)
#define FRAG_L1 0
#define FRAG_L2 256
#define FRAG_L3 1280
#define FRAG_L4 2304
#define FRAG_TOTAL 6400
__device__ uint4 g_wfrag[FRAG_TOTAL];

// ---------------------------------------------------------------------------
// mma.sync m16n8k16 row.col bf16 -> f32  (compute_103-legal, runs on HMMA)
// ---------------------------------------------------------------------------
__device__ __forceinline__ void mma16816(float* c,
                                         uint32_t a0, uint32_t a1, uint32_t a2, uint32_t a3,
                                         uint32_t b0, uint32_t b1) {
    asm volatile(
        "mma.sync.aligned.m16n8k16.row.col.f32.bf16.bf16.f32 "
        "{%0,%1,%2,%3}, {%4,%5,%6,%7}, {%8,%9}, {%0,%1,%2,%3};"
        : "+f"(c[0]), "+f"(c[1]), "+f"(c[2]), "+f"(c[3])
        : "r"(a0), "r"(a1), "r"(a2), "r"(a3), "r"(b0), "r"(b1));
}

__device__ __forceinline__ uint32_t pack2(float v0, float v1) {   // v0 -> low 16
    uint16_t u0 = __bfloat16_as_ushort(__float2bfloat16_rn(v0));
    uint16_t u1 = __bfloat16_as_ushort(__float2bfloat16_rn(v1));
    return (uint32_t)u0 | ((uint32_t)u1 << 16);
}

// Split (v0,v1) into bf16 hi pair + bf16 residual-lo pair.
__device__ __forceinline__ void split2(float v0, float v1, uint32_t& hi, uint32_t& lo) {
    __nv_bfloat16 h0 = __float2bfloat16_rn(v0);
    __nv_bfloat16 h1 = __float2bfloat16_rn(v1);
    float r0 = v0 - __bfloat162float(h0);
    float r1 = v1 - __bfloat162float(h1);
    hi = (uint32_t)__bfloat16_as_ushort(h0) | ((uint32_t)__bfloat16_as_ushort(h1) << 16);
    lo = pack2(r0, r1);
}

__device__ __forceinline__ float silu_act(float x, float act) {
    return __fdividef(x, 1.0f + __expf(-x)) * act;
}

// ---------------------------------------------------------------------------
// Setup kernel: fp32 weights -> fragment-ordered hi/lo bf16 (scales folded)
// ---------------------------------------------------------------------------
__global__ void build_frags(const float* __restrict__ w0, const float* __restrict__ w1,
                            const float* __restrict__ w2, const float* __restrict__ w3)
{
    int idx = blockIdx.x * blockDim.x + threadIdx.x;
    if (idx >= FRAG_TOTAL) return;

    const float* src; int K, N, ktiles, base; float scale;
    if (idx < FRAG_L2)      { base = FRAG_L1; src = w0; K = 8;  N = 64;  ktiles = 1; scale = 0.35355339059327373f; }
    else if (idx < FRAG_L3) { base = FRAG_L2; src = w1; K = 64; N = 64;  ktiles = 4; scale = 0.125f; }
    else if (idx < FRAG_L4) { base = FRAG_L3; src = w2; K = 64; N = 64;  ktiles = 4; scale = 0.125f; }
    else                    { base = FRAG_L4; src = w3; K = 64; N = 256; ktiles = 4; scale = 0.125f; }

    int fid  = idx - base;
    int lane = fid & 31, pair = fid >> 5;
    int kt = pair % ktiles, nt = pair / ktiles;
    int g = lane >> 2, t = lane & 3;
    int n  = nt * 8 + g;
    int kb = kt * 16 + 2 * t;
    int ks[4] = { kb, kb + 1, kb + 8, kb + 9 };

    uint16_t hi[4], lo[4];
#pragma unroll
    for (int i = 0; i < 4; i++) {
        float v = (ks[i] < K) ? src[ks[i] * N + n] * scale : 0.0f;
        __nv_bfloat16 h = __float2bfloat16_rn(v);
        float r = v - __bfloat162float(h);
        hi[i] = __bfloat16_as_ushort(h);
        lo[i] = __bfloat16_as_ushort(__float2bfloat16_rn(r));
    }
    uint4 o;
    o.x = (uint32_t)hi[0] | ((uint32_t)hi[1] << 16);   // b0 hi
    o.y = (uint32_t)hi[2] | ((uint32_t)hi[3] << 16);   // b1 hi
    o.z = (uint32_t)lo[0] | ((uint32_t)lo[1] << 16);   // b0 lo
    o.w = (uint32_t)lo[2] | ((uint32_t)lo[3] << 16);   // b1 lo
    g_wfrag[idx] = o;
}

// ---------------------------------------------------------------------------
// Kernel 1: MLP via chained warp MMAs. Warp = 16 edges, block = 8 warps.
// ---------------------------------------------------------------------------
__device__ __forceinline__ void act_split(const float* acc, uint32_t* ah, uint32_t* al,
                                          float act) {
#pragma unroll
    for (int kt = 0; kt < 4; kt++) {
        const float* T0 = acc + (2 * kt) * 4;
        const float* T1 = acc + (2 * kt + 1) * 4;
        split2(silu_act(T0[0], act), silu_act(T0[1], act), ah[kt * 4 + 0], al[kt * 4 + 0]); // a0
        split2(silu_act(T0[2], act), silu_act(T0[3], act), ah[kt * 4 + 1], al[kt * 4 + 1]); // a1
        split2(silu_act(T1[0], act), silu_act(T1[1], act), ah[kt * 4 + 2], al[kt * 4 + 2]); // a2
        split2(silu_act(T1[2], act), silu_act(T1[3], act), ah[kt * 4 + 3], al[kt * 4 + 3]); // a3
    }
}

__global__ void __launch_bounds__(256)
mlp_mma_kernel(const float* __restrict__ edge_attrs, int n_edges, float act)
{
    int lane = threadIdx.x & 31, warp = threadIdx.x >> 5;
    int g = lane >> 2, t = lane & 3;
    int row0 = blockIdx.x * 128 + warp * 16 + g;
    int row1 = row0 + 8;

    // ---- Layer 1 A fragments from edge_attrs (K=8, cols 8..15 zero) ----
    float x00 = 0.f, x01 = 0.f, x10 = 0.f, x11 = 0.f;
    if (row0 < n_edges) {
        const float* p = edge_attrs + (size_t)row0 * 11 + 2 * t;
        x00 = __ldg(p); x01 = __ldg(p + 1);
    }
    if (row1 < n_edges) {
        const float* p = edge_attrs + (size_t)row1 * 11 + 2 * t;
        x10 = __ldg(p); x11 = __ldg(p + 1);
    }
    uint32_t a0h, a0l, a1h, a1l;
    split2(x00, x01, a0h, a0l);
    split2(x10, x11, a1h, a1l);

    float acc[32];
    uint32_t ah[16], al[16];

    // ---- Layer 1: N=64, single k-tile ----
#pragma unroll
    for (int i = 0; i < 32; i++) acc[i] = 0.f;
#pragma unroll
    for (int nt = 0; nt < 8; nt++) {
        uint4 f = __ldg(&g_wfrag[FRAG_L1 + nt * 32 + lane]);
        float* c = &acc[nt * 4];
        mma16816(c, a0h, a1h, 0u, 0u, f.x, f.y);
        mma16816(c, a0h, a1h, 0u, 0u, f.z, f.w);
        mma16816(c, a0l, a1l, 0u, 0u, f.x, f.y);
    }
    act_split(acc, ah, al, act);

    // ---- Layer 2: 64x64 ----
#pragma unroll
    for (int i = 0; i < 32; i++) acc[i] = 0.f;
#pragma unroll
    for (int nt = 0; nt < 8; nt++) {
#pragma unroll
        for (int kt = 0; kt < 4; kt++) {
            uint4 f = __ldg(&g_wfrag[FRAG_L2 + (nt * 4 + kt) * 32 + lane]);
            float* c = &acc[nt * 4];
            const uint32_t* A = &ah[kt * 4];
            const uint32_t* L = &al[kt * 4];
            mma16816(c, A[0], A[1], A[2], A[3], f.x, f.y);
            mma16816(c, A[0], A[1], A[2], A[3], f.z, f.w);
            mma16816(c, L[0], L[1], L[2], L[3], f.x, f.y);
        }
    }
    act_split(acc, ah, al, act);

    // ---- Layer 3: 64x64 ----
#pragma unroll
    for (int i = 0; i < 32; i++) acc[i] = 0.f;
#pragma unroll
    for (int nt = 0; nt < 8; nt++) {
#pragma unroll
        for (int kt = 0; kt < 4; kt++) {
            uint4 f = __ldg(&g_wfrag[FRAG_L3 + (nt * 4 + kt) * 32 + lane]);
            float* c = &acc[nt * 4];
            const uint32_t* A = &ah[kt * 4];
            const uint32_t* L = &al[kt * 4];
            mma16816(c, A[0], A[1], A[2], A[3], f.x, f.y);
            mma16816(c, A[0], A[1], A[2], A[3], f.z, f.w);
            mma16816(c, L[0], L[1], L[2], L[3], f.x, f.y);
        }
    }
    act_split(acc, ah, al, act);

    // ---- Layer 4: 64x256, 4 chunks of 64 cols; no activation; store ----
#pragma unroll 1
    for (int chunk = 0; chunk < 4; chunk++) {
#pragma unroll
        for (int i = 0; i < 32; i++) acc[i] = 0.f;
#pragma unroll
        for (int nt = 0; nt < 8; nt++) {
#pragma unroll
            for (int kt = 0; kt < 4; kt++) {
                uint4 f = __ldg(&g_wfrag[FRAG_L4 + ((chunk * 8 + nt) * 4 + kt) * 32 + lane]);
                float* c = &acc[nt * 4];
                const uint32_t* A = &ah[kt * 4];
                const uint32_t* L = &al[kt * 4];
                mma16816(c, A[0], A[1], A[2], A[3], f.x, f.y);
                mma16816(c, A[0], A[1], A[2], A[3], f.z, f.w);
                mma16816(c, L[0], L[1], L[2], L[3], f.x, f.y);
            }
        }
#pragma unroll
        for (int nt = 0; nt < 8; nt++) {
            int col = (chunk * 8 + nt) * 8 + 2 * t;
            if (row0 < n_edges)
                *(float2*)(g_mix + (size_t)row0 * 256 + col) = make_float2(acc[nt * 4 + 0], acc[nt * 4 + 1]);
            if (row1 < n_edges)
                *(float2*)(g_mix + (size_t)row1 * 256 + col) = make_float2(acc[nt * 4 + 2], acc[nt * 4 + 3]);
        }
    }
}

// ---------------------------------------------------------------------------
// Kernel 2: warp-per-edge message build + vectorized scatter-add (unchanged)
// ---------------------------------------------------------------------------
__global__ void __launch_bounds__(256)
scatter_kernel(const float* __restrict__ node_feats,
               const float* __restrict__ edge_attrs,
               const int* __restrict__ senders,
               const int* __restrict__ receivers,
               float* __restrict__ out,
               int n_edges)
{
    __shared__ float msg[8][512];
    int warp = threadIdx.x >> 5;
    int lane = threadIdx.x & 31;
    int e = blockIdx.x * 8 + warp;
    if (e >= n_edges) return;

    int s = __ldg(senders + e);
    int r = __ldg(receivers + e);
    const float* ea = edge_attrs + (size_t)e * 11;
    float ev0 = __ldg(ea + 8), ev1 = __ldg(ea + 9), ev2 = __ldg(ea + 10);

    const float* nrow   = node_feats + (size_t)s * 256;
    const float* mixrow = g_mix + (size_t)e * 256;

    const float S   = 0.25f;                    // 1/sqrt(16)
    const float IS3 = 0.57735026918962576f;     // 1/sqrt(3)

#pragma unroll
    for (int tt = 0; tt < 2; tt++) {
        int m = lane + tt * 32;
        float ms = __ldg(nrow + m);
        float v0 = __ldg(nrow + 64 + 3 * m + 0);
        float v1 = __ldg(nrow + 64 + 3 * m + 1);
        float v2 = __ldg(nrow + 64 + 3 * m + 2);
        float mixA = __ldg(mixrow + m);
        float mixB = __ldg(mixrow + 64 + m);
        float mixC = __ldg(mixrow + 128 + m);
        float mixD = __ldg(mixrow + 192 + m);

        float tps = (v0 * ev0 + v1 * ev1 + v2 * ev2) * IS3;

        msg[warp][m]      = ms  * mixA * S;
        msg[warp][64 + m] = tps * mixB * S;

        float c = mixC * S;
        msg[warp][128 + 3 * m + 0] = v0 * c;
        msg[warp][128 + 3 * m + 1] = v1 * c;
        msg[warp][128 + 3 * m + 2] = v2 * c;

        float d = ms * mixD * S;
        msg[warp][320 + 3 * m + 0] = ev0 * d;
        msg[warp][320 + 3 * m + 1] = ev1 * d;
        msg[warp][320 + 3 * m + 2] = ev2 * d;
    }
    __syncwarp();

    float* orow = out + (size_t)r * 512;
    const float4* m4 = (const float4*)msg[warp];
#pragma unroll
    for (int i = 0; i < 4; i++) {
        int idx = lane + i * 32;
        float4 v = m4[idx];
        asm volatile("red.global.add.v4.f32 [%0], {%1, %2, %3, %4};"
                     :: "l"(orow + idx * 4),
                        "f"(v.x), "f"(v.y), "f"(v.z), "f"(v.w)
                     : "memory");
    }
}

// ---------------------------------------------------------------------------
// Host
// ---------------------------------------------------------------------------
static float compute_act_cst() {
    const int    N = 20000;
    const double a = -14.0, b = 14.0;
    const double h = (b - a) / N;
    double sum = 0.0;
    for (int i = 0; i <= N; i++) {
        double xx  = a + h * i;
        double sig = 1.0 / (1.0 + exp(-xx));
        double sl  = xx * sig;
        double f   = exp(-0.5 * xx * xx) * sl * sl;
        double wq  = (i == 0 || i == N) ? 1.0 : ((i & 1) ? 4.0 : 2.0);
        sum += wq * f;
    }
    sum *= h / 3.0;
    sum /= sqrt(2.0 * M_PI);
    return (float)(1.0 / sqrt(sum));
}

extern "C" void kernel_launch(void* const* d_in, const int* in_sizes, int n_in,
                              void* d_out, int out_size)
{
    const float* node_feats = (const float*)d_in[0];
    const float* edge_attrs = (const float*)d_in[1];
    const int*   senders    = (const int*)d_in[2];
    const int*   receivers  = (const int*)d_in[3];
    const float* w0         = (const float*)d_in[4];
    const float* w1         = (const float*)d_in[5];
    const float* w2         = (const float*)d_in[6];
    const float* w3         = (const float*)d_in[7];
    float*       out        = (float*)d_out;

    int n_edges = in_sizes[2];
    if (n_edges > MAX_EDGES) n_edges = MAX_EDGES;

    float act = compute_act_cst();

    cudaMemsetAsync(d_out, 0, (size_t)out_size * sizeof(float));

    build_frags<<<(FRAG_TOTAL + 255) / 256, 256>>>(w0, w1, w2, w3);

    int k1_blocks = (n_edges + 127) / 128;
    mlp_mma_kernel<<<k1_blocks, 256>>>(edge_attrs, n_edges, act);

    int k2_blocks = (n_edges + 7) / 8;
    scatter_kernel<<<k2_blocks, 256>>>(node_feats, edge_attrs, senders, receivers,
                                       out, n_edges);
}